// round 12
// baseline (speedup 1.0000x reference)
#include <cuda_runtime.h>
#include <cuda_fp16.h>
#include <cstdint>

// ---------------------------------------------------------------------------
// GCN forward:  N=50000, E=800000, F_IN=128, H=256, G=256, O=32, L=3
// edge_index / batch are int32.
//
// fp16 carried end-to-end; GEMM: mma.sync m16n8k16, 32-k smem tiles (dyn smem);
// stream join deferred past conv GEMM 1 (CSR only needed by aggregation).
// ---------------------------------------------------------------------------

#define NN 50000
#define NE 800000
#define FIN 128
#define HD 256
#define NG 256
#define NO 32
#define NL 3
#define ETOT (NE + NN)
#define SCB 49

// ----------------------------- device scratch ------------------------------
__device__ __half   g_hf16[(size_t)NN * HD];         // fp16 h (GEMM A input)
__device__ __half   g_xh[(size_t)NN * FIN];          // fp16 x
__device__ __half   g_hwh[(size_t)NN * HD];          // fp16 hw (conv GEMM out)
__device__ int      g_counts[NN];
__device__ int      g_cursor[NN];
__device__ float    g_dis[NN];
__device__ int      g_offsets[NN + 1];
__device__ int      g_part[SCB];
__device__ int2     g_csr[ETOT];
__device__ int      g_gstart[NG + 1];
__device__ uint32_t g_wp_enc[(FIN / 2) * HD];        // half2(W[2p][n],W[2p+1][n])
__device__ uint32_t g_wp_conv[NL * (HD / 2) * HD];

// ------------------------------ setup kernels ------------------------------
__global__ void k_init() {
    int i = blockIdx.x * blockDim.x + threadIdx.x;
    if (i < NN) g_counts[i] = 1;                     // self loop
}

__global__ void k_count_deg(const int* __restrict__ ei) {
    int e = blockIdx.x * blockDim.x + threadIdx.x;
    if (e < NE) atomicAdd(&g_counts[ei[NE + e]], 1);
}

__global__ void __launch_bounds__(1024) k_scan_local() {
    __shared__ int sd[1024];
    int t = threadIdx.x;
    int i = blockIdx.x * 1024 + t;
    int v = 0;
    if (i < NN) {
        v = g_counts[i];
        g_dis[i] = rsqrtf((float)v);
    }
    sd[t] = v;
    __syncthreads();
    #pragma unroll
    for (int off = 1; off < 1024; off <<= 1) {
        int tmp = (t >= off) ? sd[t - off] : 0;
        __syncthreads();
        if (t >= off) sd[t] += tmp;
        __syncthreads();
    }
    if (i < NN) g_offsets[i + 1] = sd[t];
    if (t == 1023) g_part[blockIdx.x] = sd[t];
}

// adds block-prefix of partials (mini warp scan, done redundantly per block),
// finalizes offsets, zeroes cursor
__global__ void __launch_bounds__(1024) k_scan_add() {
    __shared__ int sp[64];
    int t = threadIdx.x;
    if (t < 64) sp[t] = (t < SCB) ? g_part[t] : 0;
    __syncthreads();
    #pragma unroll
    for (int off = 1; off < 64; off <<= 1) {
        int v = (t < 64 && t >= off) ? sp[t - off] : 0;
        __syncthreads();
        if (t < 64) sp[t] += v;
        __syncthreads();
    }
    int prefix = (blockIdx.x == 0) ? 0 : sp[blockIdx.x - 1];
    int i = blockIdx.x * 1024 + t;
    if (i < NN) {
        g_offsets[i + 1] += prefix;
        g_cursor[i] = 0;
    }
    if (i == 0) g_offsets[0] = 0;
}

// merged self-loop + edge CSR fill
__global__ void k_fill(const int* __restrict__ ei) {
    int idx = blockIdx.x * blockDim.x + threadIdx.x;
    if (idx < NN) {
        int pos = g_offsets[idx] + atomicAdd(&g_cursor[idx], 1);
        float d = g_dis[idx];
        g_csr[pos] = make_int2(idx, __float_as_int(d * d));
    } else if (idx < NN + NE) {
        int e = idx - NN;
        int s = ei[e];
        int d = ei[NE + e];
        int pos = g_offsets[d] + atomicAdd(&g_cursor[d], 1);
        g_csr[pos] = make_int2(s, __float_as_int(g_dis[s] * g_dis[d]));
    }
}

// graph boundaries: gstart[g] = lower_bound(batch, g)  (batch sorted)
__global__ void k_gsearch(const int* __restrict__ batch) {
    int g = blockIdx.x * blockDim.x + threadIdx.x;
    if (g > NG) return;
    int lo = 0, hi = NN;
    while (lo < hi) {
        int mid = (lo + hi) >> 1;
        if (batch[mid] < g) lo = mid + 1; else hi = mid;
    }
    g_gstart[g] = lo;
}

// ---------------- input convert + weight pack (merged, once) ----------------
__global__ void __launch_bounds__(256) k_prep(const float* __restrict__ x,
                                              const float* __restrict__ enc_w,
                                              const float* __restrict__ conv_w) {
    int i = blockIdx.x * blockDim.x + threadIdx.x;
    const int XT  = NN * FIN / 2;
    const int NE_ = (FIN / 2) * HD;
    const int NC_ = NL * (HD / 2) * HD;
    if (i < XT) {
        float2 f = ((const float2*)x)[i];
        ((__half2*)g_xh)[i] = __floats2half2_rn(f.x, f.y);
        return;
    }
    int j = i - XT;
    if (j < NE_) {
        int p = j / HD, n = j % HD;
        __half2 h = __floats2half2_rn(enc_w[(2 * p) * HD + n],
                                      enc_w[(2 * p + 1) * HD + n]);
        g_wp_enc[j] = *reinterpret_cast<uint32_t*>(&h);
        return;
    }
    int r0 = j - NE_;
    if (r0 < NC_) {
        int l = r0 / ((HD / 2) * HD);
        int r = r0 % ((HD / 2) * HD);
        int p = r / HD, n = r % HD;
        const float* W = conv_w + (size_t)l * HD * HD;
        __half2 h = __floats2half2_rn(W[(2 * p) * HD + n],
                                      W[(2 * p + 1) * HD + n]);
        g_wp_conv[r0] = *reinterpret_cast<uint32_t*>(&h);
    }
}

// ----------------------- fp16 tensor-core GEMM ------------------------------
// Ch[M,256] = A[M,K] @ W[K,256] (+bias). Tile 128x128x32, 256 thr, 8 warps 4x2.
// Dynamic smem: As/Bs double-buffered [16][136] uint32 (kpair-major half2).
__device__ __forceinline__ void mma_f16(float* c, const uint32_t* a,
                                        uint32_t b0, uint32_t b1) {
    asm volatile(
        "mma.sync.aligned.m16n8k16.row.col.f32.f16.f16.f32 "
        "{%0,%1,%2,%3}, {%4,%5,%6,%7}, {%8,%9}, {%0,%1,%2,%3};"
        : "+f"(c[0]), "+f"(c[1]), "+f"(c[2]), "+f"(c[3])
        : "r"(a[0]), "r"(a[1]), "r"(a[2]), "r"(a[3]), "r"(b0), "r"(b1));
}

#define TILE_U32 (16 * 136)
#define GEMM_SMEM (4 * TILE_U32 * 4)   // 2 bufs x (As+Bs) x 4B = 69632 B

__global__ void __launch_bounds__(256) k_gemm_f16(
    const __half* __restrict__ A, const uint32_t* __restrict__ Wp,
    const float* __restrict__ bias, __half* __restrict__ Ch,
    int M, int K)
{
    extern __shared__ uint32_t sm[];
    // layout: As0 | As1 | Bs0 | Bs1, each 16*136 u32
    uint32_t* AsB[2] = { sm, sm + TILE_U32 };
    uint32_t* BsB[2] = { sm + 2 * TILE_U32, sm + 3 * TILE_U32 };

    int tid = threadIdx.x;
    int bm = blockIdx.x * 128;
    int bn = blockIdx.y * 128;

    int lane = tid & 31;
    int warp = tid >> 5;
    int tig  = lane & 3;
    int grp  = lane >> 2;
    int wm   = (warp & 3) * 32;
    int wn   = (warp >> 2) * 64;

    // A loader: row = tid>>1, kpair offset (tid&1)*8 (=16 halfs), 2 uint4
    int ar  = bm + (tid >> 1);  if (ar >= M) ar = M - 1;
    int ap2 = (tid & 1) * 8;
    // B loader: kpair row = tid>>4 (0..15), col (tid&15)*4 and +64, 2 uint4
    int bk  = tid >> 4;
    int bc  = (tid & 15) * 4;

    const __half*   Apt = A + (size_t)ar * K + ap2 * 2;
    const uint32_t* Bpt = Wp + (size_t)bk * HD + bn + bc;

    float acc[2][8][4];
    #pragma unroll
    for (int mt = 0; mt < 2; mt++)
        #pragma unroll
        for (int nt = 0; nt < 8; nt++)
            #pragma unroll
            for (int r = 0; r < 4; r++) acc[mt][nt][r] = 0.f;

    int KT = K >> 5;                       // 32-k tiles

    uint4 rA0 = *(const uint4*)(Apt);
    uint4 rA1 = *(const uint4*)(Apt + 8);
    uint4 rB0 = *(const uint4*)(Bpt);
    uint4 rB1 = *(const uint4*)(Bpt + 64);

    {
        int arow = tid >> 1;
        uint32_t* As = AsB[0];
        uint32_t* Bs = BsB[0];
        As[(ap2 + 0) * 136 + arow] = rA0.x;
        As[(ap2 + 1) * 136 + arow] = rA0.y;
        As[(ap2 + 2) * 136 + arow] = rA0.z;
        As[(ap2 + 3) * 136 + arow] = rA0.w;
        As[(ap2 + 4) * 136 + arow] = rA1.x;
        As[(ap2 + 5) * 136 + arow] = rA1.y;
        As[(ap2 + 6) * 136 + arow] = rA1.z;
        As[(ap2 + 7) * 136 + arow] = rA1.w;
        *(uint4*)&Bs[bk * 136 + bc]      = rB0;
        *(uint4*)&Bs[bk * 136 + bc + 64] = rB1;
    }
    __syncthreads();

    for (int kt = 0; kt < KT; kt++) {
        int cur = kt & 1;
        int nxt = cur ^ 1;
        if (kt + 1 < KT) {
            rA0 = *(const uint4*)(Apt + (kt + 1) * 32);
            rA1 = *(const uint4*)(Apt + (kt + 1) * 32 + 8);
            rB0 = *(const uint4*)(Bpt + (size_t)(kt + 1) * 16 * HD);
            rB1 = *(const uint4*)(Bpt + (size_t)(kt + 1) * 16 * HD + 64);
        }

        uint32_t* As = AsB[cur];
        uint32_t* Bs = BsB[cur];
        #pragma unroll
        for (int ks = 0; ks < 16; ks += 8) {
            uint32_t a[2][4];
            #pragma unroll
            for (int mt = 0; mt < 2; mt++) {
                int rb = wm + mt * 16 + grp;
                a[mt][0] = As[(ks + tig) * 136 + rb];
                a[mt][1] = As[(ks + tig) * 136 + rb + 8];
                a[mt][2] = As[(ks + tig + 4) * 136 + rb];
                a[mt][3] = As[(ks + tig + 4) * 136 + rb + 8];
            }
            #pragma unroll
            for (int nt = 0; nt < 8; nt++) {
                int nb = wn + nt * 8 + grp;
                uint32_t b0 = Bs[(ks + tig) * 136 + nb];
                uint32_t b1 = Bs[(ks + tig + 4) * 136 + nb];
                mma_f16(acc[0][nt], a[0], b0, b1);
                mma_f16(acc[1][nt], a[1], b0, b1);
            }
        }

        if (kt + 1 < KT) {
            int arow = tid >> 1;
            uint32_t* Asn = AsB[nxt];
            uint32_t* Bsn = BsB[nxt];
            Asn[(ap2 + 0) * 136 + arow] = rA0.x;
            Asn[(ap2 + 1) * 136 + arow] = rA0.y;
            Asn[(ap2 + 2) * 136 + arow] = rA0.z;
            Asn[(ap2 + 3) * 136 + arow] = rA0.w;
            Asn[(ap2 + 4) * 136 + arow] = rA1.x;
            Asn[(ap2 + 5) * 136 + arow] = rA1.y;
            Asn[(ap2 + 6) * 136 + arow] = rA1.z;
            Asn[(ap2 + 7) * 136 + arow] = rA1.w;
            *(uint4*)&Bsn[bk * 136 + bc]      = rB0;
            *(uint4*)&Bsn[bk * 136 + bc + 64] = rB1;
        }
        __syncthreads();
    }

    #pragma unroll
    for (int mt = 0; mt < 2; mt++) {
        #pragma unroll
        for (int nt = 0; nt < 8; nt++) {
            int col = bn + wn + nt * 8 + tig * 2;
            float b0 = bias ? bias[col]     : 0.f;
            float b1 = bias ? bias[col + 1] : 0.f;
            int r0 = bm + wm + mt * 16 + grp;
            int r1 = r0 + 8;
            if (r0 < M) {
                __half2 v = __floats2half2_rn(acc[mt][nt][0] + b0,
                                              acc[mt][nt][1] + b1);
                *(__half2*)(Ch + (size_t)r0 * HD + col) = v;
            }
            if (r1 < M) {
                __half2 v = __floats2half2_rn(acc[mt][nt][2] + b0,
                                              acc[mt][nt][3] + b1);
                *(__half2*)(Ch + (size_t)r1 * HD + col) = v;
            }
        }
    }
}

// ----------------------------- CSR aggregation -----------------------------
// 8 nodes/block; 32 threads/node; uint4 = 8 fp16 features/thread; fp32 acc.
__global__ void __launch_bounds__(256) k_aggregate(const float* __restrict__ bias) {
    int grpIdx = threadIdx.x >> 5;
    int t      = threadIdx.x & 31;
    int i = blockIdx.x * 8 + grpIdx;
    if (i >= NN) return;
    int beg = g_offsets[i];
    int end = g_offsets[i + 1];

    float acc[8], acc2[8];
    {
        float4 bA = ((const float4*)bias)[t * 2];
        float4 bB = ((const float4*)bias)[t * 2 + 1];
        acc[0] = bA.x; acc[1] = bA.y; acc[2] = bA.z; acc[3] = bA.w;
        acc[4] = bB.x; acc[5] = bB.y; acc[6] = bB.z; acc[7] = bB.w;
        #pragma unroll
        for (int j = 0; j < 8; j++) acc2[j] = 0.f;
    }

    const uint4* hwv = (const uint4*)g_hwh;
    int e = beg;
    for (; e + 2 <= end; e += 2) {
        int2 p0 = __ldg(&g_csr[e]);
        int2 p1 = __ldg(&g_csr[e + 1]);
        float w0 = __int_as_float(p0.y);
        float w1 = __int_as_float(p1.y);
        uint4 v0 = __ldg(&hwv[(size_t)p0.x * 32 + t]);
        uint4 v1 = __ldg(&hwv[(size_t)p1.x * 32 + t]);
        const __half2* h0 = (const __half2*)&v0;
        const __half2* h1 = (const __half2*)&v1;
        #pragma unroll
        for (int j = 0; j < 4; j++) {
            float2 f0 = __half22float2(h0[j]);
            float2 f1 = __half22float2(h1[j]);
            acc[2*j]   = fmaf(w0, f0.x, acc[2*j]);
            acc[2*j+1] = fmaf(w0, f0.y, acc[2*j+1]);
            acc2[2*j]   = fmaf(w1, f1.x, acc2[2*j]);
            acc2[2*j+1] = fmaf(w1, f1.y, acc2[2*j+1]);
        }
    }
    if (e < end) {
        int2 p = __ldg(&g_csr[e]);
        float w = __int_as_float(p.y);
        uint4 v = __ldg(&hwv[(size_t)p.x * 32 + t]);
        const __half2* hh = (const __half2*)&v;
        #pragma unroll
        for (int j = 0; j < 4; j++) {
            float2 f = __half22float2(hh[j]);
            acc[2*j]   = fmaf(w, f.x, acc[2*j]);
            acc[2*j+1] = fmaf(w, f.y, acc[2*j+1]);
        }
    }
    #pragma unroll
    for (int j = 0; j < 8; j++) acc[j] += acc2[j];

    uint4 ho;
    __half2 q0 = __floats2half2_rn(acc[0], acc[1]);
    __half2 q1 = __floats2half2_rn(acc[2], acc[3]);
    __half2 q2 = __floats2half2_rn(acc[4], acc[5]);
    __half2 q3 = __floats2half2_rn(acc[6], acc[7]);
    ho.x = *reinterpret_cast<uint32_t*>(&q0);
    ho.y = *reinterpret_cast<uint32_t*>(&q1);
    ho.z = *reinterpret_cast<uint32_t*>(&q2);
    ho.w = *reinterpret_cast<uint32_t*>(&q3);
    ((uint4*)g_hf16)[(size_t)i * 32 + t] = ho;
}

// --------------------- fused pooling + readout MLP --------------------------
__global__ void __launch_bounds__(HD) k_pool_readout(
    const float* __restrict__ r1w, const float* __restrict__ r1b,
    const float* __restrict__ r2w, const float* __restrict__ r2b,
    float* __restrict__ out)
{
    int g = blockIdx.x;
    int t = threadIdx.x;
    int beg = g_gstart[g], end = g_gstart[g + 1];
    float s = 0.f, m = -3.402823e38f;
    const __half* hp = g_hf16 + t;
    for (int i = beg; i < end; ++i) {
        float v = __half2float(hp[(size_t)i * HD]);
        s += v;
        m = fmaxf(m, v);
    }
    int cnt = end - beg;
    __shared__ float sh[3 * HD];
    sh[t]          = s;
    sh[HD + t]     = (cnt > 0) ? m : 0.f;
    sh[2 * HD + t] = s / (float)(cnt > 0 ? cnt : 1);
    __syncthreads();

    __shared__ float z[128];
    if (t < 128) {
        float acc = r1b[t];
        for (int k = 0; k < 3 * HD; k++)
            acc = fmaf(sh[k], r1w[k * 128 + t], acc);
        z[t] = (acc > 0.f) ? acc : 0.01f * acc;   // leaky_relu(0.01)
    }
    __syncthreads();
    if (t < NO) {
        float o = r2b[t];
        #pragma unroll 4
        for (int k = 0; k < 128; k++)
            o = fmaf(z[k], r2w[k * NO + t], o);
        out[g * NO + t] = o;
    }
}

// -------------------------------- launcher ---------------------------------
extern "C" void kernel_launch(void* const* d_in, const int* in_sizes, int n_in,
                              void* d_out, int out_size)
{
    const float* x      = (const float*)d_in[0];
    const int*   ei     = (const int*)d_in[1];
    const int*   batch  = (const int*)d_in[2];
    const float* enc_w  = (const float*)d_in[3];
    const float* enc_b  = (const float*)d_in[4];
    const float* conv_w = (const float*)d_in[5];
    const float* conv_b = (const float*)d_in[6];
    const float* r1_w   = (const float*)d_in[7];
    const float* r1_b   = (const float*)d_in[8];
    const float* r2_w   = (const float*)d_in[9];
    const float* r2_b   = (const float*)d_in[10];
    float* out = (float*)d_out;

    __half *hf16, *xh, *hwh;
    uint32_t *wp_enc, *wp_conv;
    cudaGetSymbolAddress((void**)&hf16, g_hf16);
    cudaGetSymbolAddress((void**)&xh,   g_xh);
    cudaGetSymbolAddress((void**)&hwh,  g_hwh);
    cudaGetSymbolAddress((void**)&wp_enc,  g_wp_enc);
    cudaGetSymbolAddress((void**)&wp_conv, g_wp_conv);

    static cudaStream_t s_side = nullptr;
    static cudaEvent_t  ev_fork = nullptr, ev_join = nullptr;
    if (!s_side) {
        cudaStreamCreateWithFlags(&s_side, cudaStreamNonBlocking);
        cudaEventCreateWithFlags(&ev_fork, cudaEventDisableTiming);
        cudaEventCreateWithFlags(&ev_join, cudaEventDisableTiming);
        cudaFuncSetAttribute(k_gemm_f16,
                             cudaFuncAttributeMaxDynamicSharedMemorySize,
                             GEMM_SMEM);
    }

    const int TB = 256;
    int gN = (NN + TB - 1) / TB;
    int gE = (NE + TB - 1) / TB;
    dim3 grid((NN + 127) / 128, HD / 128);

    // init on origin stream, then fork CSR chain to side stream
    k_init<<<gN, TB>>>();
    cudaEventRecord(ev_fork, 0);
    cudaStreamWaitEvent(s_side, ev_fork, 0);

    // side: CSR build chain (needed only by first k_aggregate)
    k_count_deg<<<gE, TB, 0, s_side>>>(ei);
    k_scan_local<<<SCB, 1024, 0, s_side>>>();
    k_scan_add<<<SCB, 1024, 0, s_side>>>();
    k_fill<<<(ETOT + TB - 1) / TB, TB, 0, s_side>>>(ei);
    cudaEventRecord(ev_join, s_side);

    // origin: convert+pack, encoder GEMM, graph bounds, conv GEMM 1
    {
        int total = NN * FIN / 2 + (FIN / 2) * HD + NL * (HD / 2) * HD;
        k_prep<<<(total + TB - 1) / TB, TB>>>(x, enc_w, conv_w);
    }
    k_gemm_f16<<<grid, 256, GEMM_SMEM>>>(xh, wp_enc, enc_b, hf16, NN, FIN);
    k_gsearch<<<1, 512>>>(batch);
    k_gemm_f16<<<grid, 256, GEMM_SMEM>>>(hf16, wp_conv, nullptr, hwh, NN, HD);

    // join: CSR must be ready before the first aggregate
    cudaStreamWaitEvent(0, ev_join, 0);

    k_aggregate<<<(NN + 7) / 8, 256>>>(conv_b);

    for (int l = 1; l < NL; l++) {
        k_gemm_f16<<<grid, 256, GEMM_SMEM>>>(hf16, wp_conv + (size_t)l * (HD / 2) * HD,
                                             nullptr, hwh, NN, HD);
        k_aggregate<<<(NN + 7) / 8, 256>>>(conv_b + (size_t)l * HD);
    }

    // fused pooling + readout
    k_pool_readout<<<NG, HD>>>(r1_w, r1_b, r2_w, r2_b, out);
}